// round 1
// baseline (speedup 1.0000x reference)
#include <cuda_runtime.h>

// UpsampleNearest4D: x (2,8,8,16,64,64) f32, scale=2 on axes 2..5
// -> out (2,8,16,32,128,128) f32.
//
// One thread: load one input float2 (x-pair), write 8 float4s
// (2x2x2 replication over T,Z,Y; x-replication folded into the float4).
//
// Input  strides (floats): x:1, y:64, z:4096, t:65536, c:524288, b:4194304
//   -> fold (b,c) into bc with stride 524288 (b stride = 8*c stride).
// Output strides (floats): x:1, y:128, z:16384, t:524288, c:8388608, b:67108864
//   -> bc stride 8388608.

#define THREADS 256
#define N_IN_FLOAT2 (8388608u / 2u)   // 4,194,304 threads total

__global__ void __launch_bounds__(THREADS)
upsample4d_x2_kernel(const float* __restrict__ in, float* __restrict__ out) {
    unsigned i2 = blockIdx.x * THREADS + threadIdx.x;   // input float2 index

    // Decompose (all power-of-2 dims -> shifts/masks)
    unsigned x2 = i2 & 31u;           // 32 float2 per input X-row (64 floats)
    unsigned y  = (i2 >> 5)  & 63u;   // Y: 64
    unsigned z  = (i2 >> 11) & 15u;   // Z: 16
    unsigned t  = (i2 >> 15) & 7u;    // T: 8
    unsigned bc = (i2 >> 18);         // B*C: 16 (b*8 + c)

    // Input float offset
    unsigned in_off = bc * 524288u + t * 65536u + z * 4096u + y * 64u + x2 * 2u;
    float2 v = *reinterpret_cast<const float2*>(in + in_off);

    float4 w = make_float4(v.x, v.x, v.y, v.y);

    // Output base: coords doubled on t,z,y; x handled inside the float4
    unsigned out_base = bc * 8388608u + t * 1048576u + z * 32768u
                      + y * 256u + x2 * 4u;

    float* o = out + out_base;
#pragma unroll
    for (unsigned dt = 0; dt < 2; ++dt) {
#pragma unroll
        for (unsigned dz = 0; dz < 2; ++dz) {
#pragma unroll
            for (unsigned dy = 0; dy < 2; ++dy) {
                *reinterpret_cast<float4*>(
                    o + dt * 524288u + dz * 16384u + dy * 128u) = w;
            }
        }
    }
}

extern "C" void kernel_launch(void* const* d_in, const int* in_sizes, int n_in,
                              void* d_out, int out_size) {
    const float* x = (const float*)d_in[0];
    float* out = (float*)d_out;
    // scale_factor (d_in[1]) is fixed at 2 for this problem's shapes; hardcoded.
    unsigned blocks = N_IN_FLOAT2 / THREADS;   // 16384
    upsample4d_x2_kernel<<<blocks, THREADS>>>(x, out);
}

// round 8
// speedup vs baseline: 1.0123x; 1.0123x over previous
#include <cuda_runtime.h>

// UpsampleNearest4D: x (2,8,8,16,64,64) f32, scale=2 on axes 2..5
// -> out (2,8,16,32,128,128) f32.
//
// Output-major mapping for maximal DRAM write sequentiality:
//   one thread = one output float4 (4 floats along X), replicated over the
//   dy pair (+512 B), so each warp writes 2 contiguous 512 B rows and
//   consecutive warps/blocks form long sequential write streams.
//   x-replication folded into the float4: {v.x, v.x, v.y, v.y}.
//
// Each input float2 is read 4x (dt x dz); readers are 8 / 256 block-indices
// apart so repeats hit L2 (input = 32 MB << 126 MB L2). Stores use __stcs
// (evict-first) to keep the write stream from evicting input lines.
//
// Input  strides (floats): x:1, y:64, z:4096, t:65536, bc:524288  (bc = b*8+c)
// Output strides (floats): x:1, y:128, z:16384, t:524288, bc:8388608

#define THREADS 256u
#define N_THREADS_TOTAL 16777216u   // out float4s / 2 (dy pair) = 2^24

__global__ void __launch_bounds__(256)
upsample4d_x2_outmajor(const float* __restrict__ in, float* __restrict__ out) {
    unsigned i = blockIdx.x * THREADS + threadIdx.x;

    // Decompose output coords (power-of-2 dims -> shifts/masks)
    unsigned x4 = i & 31u;            // 32 float4 per output X-row (128 floats)
    unsigned yh = (i >> 5)  & 63u;    // output y-pair index == input y (64)
    unsigned oz = (i >> 11) & 31u;    // output Z: 32
    unsigned ot = (i >> 16) & 15u;    // output T: 16
    unsigned bc = (i >> 20);          // B*C: 16

    // Input offset: t = ot>>1, z = oz>>1, y = yh, x2 = x4 (2 floats per float4)
    unsigned in_off = bc * 524288u + (ot >> 1) * 65536u + (oz >> 1) * 4096u
                    + yh * 64u + x4 * 2u;
    float2 v = __ldg(reinterpret_cast<const float2*>(in + in_off));

    float4 w = make_float4(v.x, v.x, v.y, v.y);

    // Output offset: rows 2*yh and 2*yh+1
    unsigned out_off = bc * 8388608u + ot * 524288u + oz * 16384u
                     + (yh << 1) * 128u + x4 * 4u;

    __stcs(reinterpret_cast<float4*>(out + out_off), w);
    __stcs(reinterpret_cast<float4*>(out + out_off + 128u), w);
}

extern "C" void kernel_launch(void* const* d_in, const int* in_sizes, int n_in,
                              void* d_out, int out_size) {
    const float* x = (const float*)d_in[0];
    float* out = (float*)d_out;
    // scale_factor (d_in[1]) fixed at 2 for this problem's shapes; hardcoded.
    unsigned blocks = N_THREADS_TOTAL / THREADS;   // 65536
    upsample4d_x2_outmajor<<<blocks, THREADS>>>(x, out);
}